// round 4
// baseline (speedup 1.0000x reference)
#include <cuda_runtime.h>
#include <math.h>

#define NH 12
#define NB 2
#define SQ 1024
#define DM 768
#define DK 64
#define NKEYS 32
#define NBH (NB*NH)            // 24
#define NROWS (NBH*SQ)         // 24576
#define NTOT (NBH*SQ*SQ)       // 25165824

// ---- scratch (static __device__ arrays; no allocation allowed) ----
__device__ uint4    g_keys[NKEYS];
__device__ float    g_q[NBH*SQ*DK];
__device__ float    g_k[NBH*SQ*DK];
__device__ float    g_v[NBH*SQ*DK];
__device__ unsigned g_w[NTOT];        // pass 1: uint thresholds; pass 2: float avg (bits)
__device__ float    g_scale[NROWS];
__device__ float    g_attn[NBH*SQ*DK];

__device__ __forceinline__ unsigned rotl32(unsigned x, int r) {
    return __funnelshift_l(x, x, r);
}

// Threefry-2x32, 20 rounds. Caller must pre-add (x0 += k0, x1 += k1).
#define TF_ROUNDS(x0,x1,k0,k1,k2) do { \
  x0 += x1; x1 = rotl32(x1,13); x1 ^= x0; \
  x0 += x1; x1 = rotl32(x1,15); x1 ^= x0; \
  x0 += x1; x1 = rotl32(x1,26); x1 ^= x0; \
  x0 += x1; x1 = rotl32(x1, 6); x1 ^= x0; \
  x0 += k1; x1 += k2 + 1u;               \
  x0 += x1; x1 = rotl32(x1,17); x1 ^= x0; \
  x0 += x1; x1 = rotl32(x1,29); x1 ^= x0; \
  x0 += x1; x1 = rotl32(x1,16); x1 ^= x0; \
  x0 += x1; x1 = rotl32(x1,24); x1 ^= x0; \
  x0 += k2; x1 += k0 + 2u;               \
  x0 += x1; x1 = rotl32(x1,13); x1 ^= x0; \
  x0 += x1; x1 = rotl32(x1,15); x1 ^= x0; \
  x0 += x1; x1 = rotl32(x1,26); x1 ^= x0; \
  x0 += x1; x1 = rotl32(x1, 6); x1 ^= x0; \
  x0 += k0; x1 += k1 + 3u;               \
  x0 += x1; x1 = rotl32(x1,17); x1 ^= x0; \
  x0 += x1; x1 = rotl32(x1,29); x1 ^= x0; \
  x0 += x1; x1 = rotl32(x1,16); x1 ^= x0; \
  x0 += x1; x1 = rotl32(x1,24); x1 ^= x0; \
  x0 += k1; x1 += k2 + 4u;               \
  x0 += x1; x1 = rotl32(x1,13); x1 ^= x0; \
  x0 += x1; x1 = rotl32(x1,15); x1 ^= x0; \
  x0 += x1; x1 = rotl32(x1,26); x1 ^= x0; \
  x0 += x1; x1 = rotl32(x1, 6); x1 ^= x0; \
  x0 += k2; x1 += k0 + 5u;               \
} while(0)

// ---- child keys: jax.random.split(key(42), 32), partitionable fold-like ----
// child_k = threefry2x32(parent=(0,42), x0=hi(k)=0, x1=lo(k)=k)
__global__ void init_keys() {
    unsigned t = threadIdx.x;
    if (t >= NKEYS) return;
    unsigned k0 = 0u, k1 = 42u;
    unsigned k2 = k0 ^ k1 ^ 0x1BD11BDAu;
    unsigned x0 = 0u + k0;
    unsigned x1 = t + k1;
    TF_ROUNDS(x0, x1, k0, k1, k2);
    g_keys[t] = make_uint4(x0, x1, x0 ^ x1 ^ 0x1BD11BDAu, 0u);
}

// ---- QKV projection: C[b,h,s,d] = sum_k x[b,s,k]*W[h*64+d,k] + bias ----
// C = A(2048x768) * W(768x768)^T, scattered into (B,H,S,dk) layout.
__global__ void k_qkv(const float* __restrict__ X, const float* __restrict__ W,
                      const float* __restrict__ bias, int which) {
    __shared__ float As[16][65];
    __shared__ float Bs[16][65];
    float* C = (which == 0) ? g_q : ((which == 1) ? g_k : g_v);
    int tid = threadIdx.x;
    int tx = tid & 15, ty = tid >> 4;
    int m0 = blockIdx.y * 64, n0 = blockIdx.x * 64;
    int lr = tid >> 2;           // 0..63
    int lc = (tid & 3) << 2;     // 0,4,8,12
    float acc[4][4] = {};
    for (int kb = 0; kb < DM; kb += 16) {
        float4 a4 = *(const float4*)(X + (size_t)(m0 + lr) * DM + kb + lc);
        float4 b4 = *(const float4*)(W + (size_t)(n0 + lr) * DM + kb + lc);
        As[lc+0][lr] = a4.x; As[lc+1][lr] = a4.y; As[lc+2][lr] = a4.z; As[lc+3][lr] = a4.w;
        Bs[lc+0][lr] = b4.x; Bs[lc+1][lr] = b4.y; Bs[lc+2][lr] = b4.z; Bs[lc+3][lr] = b4.w;
        __syncthreads();
        #pragma unroll
        for (int kk = 0; kk < 16; kk++) {
            float a[4], b[4];
            #pragma unroll
            for (int u = 0; u < 4; u++) a[u] = As[kk][ty*4 + u];
            #pragma unroll
            for (int v = 0; v < 4; v++) b[v] = Bs[kk][tx*4 + v];
            #pragma unroll
            for (int u = 0; u < 4; u++)
                #pragma unroll
                for (int v = 0; v < 4; v++)
                    acc[u][v] += a[u] * b[v];
        }
        __syncthreads();
    }
    #pragma unroll
    for (int u = 0; u < 4; u++) {
        int m = m0 + ty*4 + u;
        int b = m >> 10, s = m & 1023;
        #pragma unroll
        for (int v = 0; v < 4; v++) {
            int n = n0 + tx*4 + v;
            int h = n >> 6, d = n & 63;
            C[(((b*NH + h) << 10) + s) * DK + d] = acc[u][v] + bias[n];
        }
    }
}

// ---- scores -> sigmoid -> integer threshold: g_w[i] = ceil(p*2^23)<<9 ----
__global__ void k_scores() {
    __shared__ float Qs[64][65];
    __shared__ float Ks[64][65];
    int bh = blockIdx.z;
    int q0 = blockIdx.y * 64, c0 = blockIdx.x * 64;
    int tid = threadIdx.x, tx = tid & 15, ty = tid >> 4;
    const float* Qp = g_q + ((size_t)bh * SQ + q0) * DK;
    const float* Kp = g_k + ((size_t)bh * SQ + c0) * DK;
    for (int e = tid; e < 4096; e += 256) {
        int d = e & 63, r = e >> 6;
        Qs[d][r] = Qp[r * DK + d];
        Ks[d][r] = Kp[r * DK + d];
    }
    __syncthreads();
    float acc[4][4] = {};
    #pragma unroll 16
    for (int d = 0; d < 64; d++) {
        float a[4], b[4];
        #pragma unroll
        for (int u = 0; u < 4; u++) a[u] = Qs[d][ty*4 + u];
        #pragma unroll
        for (int v = 0; v < 4; v++) b[v] = Ks[d][tx*4 + v];
        #pragma unroll
        for (int u = 0; u < 4; u++)
            #pragma unroll
            for (int v = 0; v < 4; v++)
                acc[u][v] += a[u] * b[v];
    }
    #pragma unroll
    for (int u = 0; u < 4; u++) {
        int q = q0 + ty*4 + u;
        #pragma unroll
        for (int v = 0; v < 4; v++) {
            int c = c0 + tx*4 + v;
            float sc = acc[u][v] * 0.125f;          // 1/sqrt(64), BETA=1
            float p = 1.0f / (1.0f + expf(-sc));
            float tf = ceilf(p * 8388608.0f);        // p*2^23 exact in fp32
            unsigned thr = (tf >= 8388608.0f) ? 0xFFFFFFFFu : (((unsigned)tf) << 9);
            g_w[((size_t)bh * SQ + q) * SQ + c] = thr;
        }
    }
}

// ---- Monte-Carlo sampler: 32 threefry draws per entry, 2 entries/thread ----
// partitionable random_bits: bits(i) = y0^y1 of threefry2x32(child_key, 0, i)
__global__ void k_sampler() {
    __shared__ uint4 sk[NKEYS];
    if (threadIdx.x < NKEYS) sk[threadIdx.x] = g_keys[threadIdx.x];
    __syncthreads();
    unsigned t = blockIdx.x * 256u + threadIdx.x;   // 0 .. NTOT/2-1
    unsigned i0 = 2u * t;
    uint2 th = *(const uint2*)(g_w + i0);
    unsigned thr0 = th.x, thr1 = th.y;
    unsigned c0 = 0u, c1 = 0u;
    #pragma unroll 4
    for (int j = 0; j < NKEYS; j++) {
        uint4 kk = sk[j];
        unsigned a0 = kk.x, a1 = i0 + kk.y;         // x0 = 0 + k0 ; x1 = idx + k1
        unsigned b0 = kk.x, b1 = a1 + 1u;
        TF_ROUNDS(a0, a1, kk.x, kk.y, kk.z);
        TF_ROUNDS(b0, b1, kk.x, kk.y, kk.z);
        unsigned ya = a0 ^ a1;
        unsigned yb = b0 ^ b1;
        c0 += (ya < thr0) ? 1u : 0u;                // == (bits>>9)*2^-23 < p
        c1 += (yb < thr1) ? 1u : 0u;
    }
    float* wf = (float*)g_w;
    float2 out;
    out.x = (float)c0 * 0.03125f;
    out.y = (float)c1 * 0.03125f;
    *(float2*)(wf + i0) = out;                       // avg, exact multiple of 1/32
}

// ---- per-row 1/rowsum (rowsum exact: multiples of 1/32, < 2^24 scaled) ----
__global__ void k_rowscale() {
    int row = blockIdx.x * 8 + (threadIdx.x >> 5);
    int lane = threadIdx.x & 31;
    const float* w = (const float*)g_w + (size_t)row * SQ;
    float s = 0.0f;
    for (int j = lane; j < SQ; j += 32) s += w[j];
    #pragma unroll
    for (int o = 16; o; o >>= 1) s += __shfl_xor_sync(0xffffffffu, s, o);
    if (lane == 0) g_scale[row] = (s > 0.0f) ? (1.0f / s) : 0.0f;
}

// ---- attn = (avg @ V) * (1/rowsum), per (b,h): 1024x64, K=1024 ----
__global__ void k_attn() {
    __shared__ float Ws[16][65];
    __shared__ float Vs[16][65];
    int bh = blockIdx.y;
    int q0 = blockIdx.x * 64;
    int tid = threadIdx.x, tx = tid & 15, ty = tid >> 4;
    int lr = tid >> 2, lc = (tid & 3) << 2;
    const float* wp = (const float*)g_w + ((size_t)bh * SQ + q0) * SQ;
    const float* vp = g_v + (size_t)bh * SQ * DK;
    float acc[4][4] = {};
    for (int kc = 0; kc < SQ; kc += 16) {
        float4 a4 = *(const float4*)(wp + (size_t)lr * SQ + kc + lc);
        Ws[lc+0][lr] = a4.x; Ws[lc+1][lr] = a4.y; Ws[lc+2][lr] = a4.z; Ws[lc+3][lr] = a4.w;
        #pragma unroll
        for (int r = 0; r < 4; r++) {
            int ee = tid + r * 256;
            int d = ee & 63, kx = ee >> 6;
            Vs[kx][d] = vp[(size_t)(kc + kx) * DK + d];
        }
        __syncthreads();
        #pragma unroll
        for (int kk = 0; kk < 16; kk++) {
            float a[4], b[4];
            #pragma unroll
            for (int u = 0; u < 4; u++) a[u] = Ws[kk][ty*4 + u];
            #pragma unroll
            for (int v = 0; v < 4; v++) b[v] = Vs[kk][tx*4 + v];
            #pragma unroll
            for (int u = 0; u < 4; u++)
                #pragma unroll
                for (int v = 0; v < 4; v++)
                    acc[u][v] += a[u] * b[v];
        }
        __syncthreads();
    }
    #pragma unroll
    for (int u = 0; u < 4; u++) {
        int q = q0 + ty*4 + u;
        float sc = g_scale[bh * SQ + q];
        #pragma unroll
        for (int v = 0; v < 4; v++)
            g_attn[((size_t)bh * SQ + q) * DK + tx*4 + v] = acc[u][v] * sc;
    }
}

// ---- output projection: out = attn2d @ Wo^T + bo (gather (b,h,s,d)->(m,c)) ----
__global__ void k_outp(const float* __restrict__ Wo, const float* __restrict__ bo,
                       float* __restrict__ out) {
    __shared__ float As[16][65];
    __shared__ float Bs[16][65];
    int tid = threadIdx.x;
    int tx = tid & 15, ty = tid >> 4;
    int m0 = blockIdx.y * 64, n0 = blockIdx.x * 64;
    int lr = tid >> 2;
    int lc = (tid & 3) << 2;
    float acc[4][4] = {};
    for (int kb = 0; kb < DM; kb += 16) {
        int m = m0 + lr;
        int c = kb + lc;                  // c..c+3 stay within one 64-block (kb%16==0, lc<=12)
        int b = m >> 10, s = m & 1023, h = c >> 6, d = c & 63;
        float4 a4 = *(const float4*)(g_attn + ((size_t)((b*NH + h) << 10) + s) * DK + d);
        float4 b4 = *(const float4*)(Wo + (size_t)(n0 + lr) * DM + kb + lc);
        As[lc+0][lr] = a4.x; As[lc+1][lr] = a4.y; As[lc+2][lr] = a4.z; As[lc+3][lr] = a4.w;
        Bs[lc+0][lr] = b4.x; Bs[lc+1][lr] = b4.y; Bs[lc+2][lr] = b4.z; Bs[lc+3][lr] = b4.w;
        __syncthreads();
        #pragma unroll
        for (int kk = 0; kk < 16; kk++) {
            float a[4], b[4];
            #pragma unroll
            for (int u = 0; u < 4; u++) a[u] = As[kk][ty*4 + u];
            #pragma unroll
            for (int v = 0; v < 4; v++) b[v] = Bs[kk][tx*4 + v];
            #pragma unroll
            for (int u = 0; u < 4; u++)
                #pragma unroll
                for (int v = 0; v < 4; v++)
                    acc[u][v] += a[u] * b[v];
        }
        __syncthreads();
    }
    #pragma unroll
    for (int u = 0; u < 4; u++) {
        int m = m0 + ty*4 + u;
        #pragma unroll
        for (int v = 0; v < 4; v++) {
            int n = n0 + tx*4 + v;
            out[(size_t)m * DM + n] = acc[u][v] + bo[n];
        }
    }
}

extern "C" void kernel_launch(void* const* d_in, const int* in_sizes, int n_in,
                              void* d_out, int out_size) {
    const float* x  = (const float*)d_in[0];
    const float* Wq = (const float*)d_in[1];
    const float* bq = (const float*)d_in[2];
    const float* Wk = (const float*)d_in[3];
    const float* bk = (const float*)d_in[4];
    const float* Wv = (const float*)d_in[5];
    const float* bv = (const float*)d_in[6];
    const float* Wo = (const float*)d_in[7];
    const float* bo = (const float*)d_in[8];
    float* out = (float*)d_out;

    init_keys<<<1, 32>>>();

    dim3 gproj(DM / 64, (NB * SQ) / 64);           // (12, 32)
    k_qkv<<<gproj, 256>>>(x, Wq, bq, 0);
    k_qkv<<<gproj, 256>>>(x, Wk, bk, 1);
    k_qkv<<<gproj, 256>>>(x, Wv, bv, 2);

    dim3 gsc(SQ / 64, SQ / 64, NBH);               // (16, 16, 24)
    k_scores<<<gsc, 256>>>();

    k_sampler<<<(NTOT / 2) / 256, 256>>>();        // 49152 blocks

    k_rowscale<<<NROWS / 8, 256>>>();              // 3072 blocks

    dim3 gat(SQ / 64, NBH);                        // (16, 24)
    k_attn<<<gat, 256>>>();

    k_outp<<<gproj, 256>>>(Wo, bo, out);
}